// round 14
// baseline (speedup 1.0000x reference)
#include <cuda_runtime.h>
#include <cuda_bf16.h>
#include <stdint.h>
#include <math.h>

// ---------------------------------------------------------------------------
// GQAWithKVCache — round 13: HMMA bf16x3 everywhere.
//   vs R13-best: X4 ldmatrix for B-frags (mm + flash), Q-rope fused into
//   flash, all weight transposes fused into one vectorized launch.
// Shapes: B=1, S=2048, D_MODEL=2048, HQ=32, HKV=8, HD=64.
// ---------------------------------------------------------------------------

#define S_LEN   2048
#define DMODEL  2048
#define HQ      32
#define HKV     8
#define HD      64
#define KVDIM   (HKV * HD)   // 512

// ------------------------- scratch (no allocations) ------------------------
__device__ __align__(16) __nv_bfloat16 g_h_hi[S_LEN * DMODEL];
__device__ __align__(16) __nv_bfloat16 g_h_lo[S_LEN * DMODEL];
__device__ __align__(16) __nv_bfloat16 g_wqT_hi[DMODEL * DMODEL];  // [N][K]
__device__ __align__(16) __nv_bfloat16 g_wqT_lo[DMODEL * DMODEL];
__device__ __align__(16) __nv_bfloat16 g_wkT_hi[KVDIM * DMODEL];
__device__ __align__(16) __nv_bfloat16 g_wkT_lo[KVDIM * DMODEL];
__device__ __align__(16) __nv_bfloat16 g_wvT_hi[KVDIM * DMODEL];
__device__ __align__(16) __nv_bfloat16 g_wvT_lo[KVDIM * DMODEL];
__device__ __align__(16) __nv_bfloat16 g_woT_hi[DMODEL * DMODEL];
__device__ __align__(16) __nv_bfloat16 g_woT_lo[DMODEL * DMODEL];
__device__ __align__(16) __nv_bfloat16 g_o_hi[S_LEN * DMODEL];
__device__ __align__(16) __nv_bfloat16 g_o_lo[S_LEN * DMODEL];
__device__ float g_q[S_LEN * DMODEL];
__device__ float g_k[S_LEN * KVDIM];
__device__ float g_v[S_LEN * KVDIM];
__device__ __align__(16) __nv_bfloat16 g_kh[S_LEN * KVDIM];    // roped
__device__ __align__(16) __nv_bfloat16 g_kl[S_LEN * KVDIM];
__device__ __align__(16) __nv_bfloat16 g_vth[KVDIM * S_LEN];   // [h][d][s]
__device__ __align__(16) __nv_bfloat16 g_vtl[KVDIM * S_LEN];

// ------------------------------ PTX helpers --------------------------------
__device__ __forceinline__ uint32_t smem_u32(const void* p) {
  uint32_t a;
  asm("{ .reg .u64 t; cvta.to.shared.u64 t, %1; cvt.u32.u64 %0, t; }"
      : "=r"(a) : "l"(p));
  return a;
}

#define SWZ128(x) ((x) ^ (((x) >> 3) & 0x70))

#define CP_ASYNC16(dst, src) \
  asm volatile("cp.async.cg.shared.global [%0], [%1], 16;" \
               :: "r"(dst), "l"(src) : "memory")
#define CP_COMMIT() asm volatile("cp.async.commit_group;" ::: "memory")
#define CP_WAIT0()  asm volatile("cp.async.wait_group 0;" ::: "memory")
#define CP_WAIT1()  asm volatile("cp.async.wait_group 1;" ::: "memory")

#define LDSM_X4(r0, r1, r2, r3, addr)                                     \
  asm volatile("ldmatrix.sync.aligned.m8n8.x4.shared.b16 {%0,%1,%2,%3}, [%4];" \
               : "=r"(r0), "=r"(r1), "=r"(r2), "=r"(r3) : "r"(addr))

#define MMA16816(c, a, b)                                                 \
  asm volatile(                                                           \
      "mma.sync.aligned.m16n8k16.row.col.f32.bf16.bf16.f32 "              \
      "{%0,%1,%2,%3},{%4,%5,%6,%7},{%8,%9},{%0,%1,%2,%3};"                \
      : "+f"((c)[0]), "+f"((c)[1]), "+f"((c)[2]), "+f"((c)[3])            \
      : "r"((a)[0]), "r"((a)[1]), "r"((a)[2]), "r"((a)[3]),               \
        "r"((b)[0]), "r"((b)[1]))

__device__ __forceinline__ uint32_t pack2bf(__nv_bfloat16 lo, __nv_bfloat16 hi) {
  uint16_t a = *(uint16_t*)&lo, b = *(uint16_t*)&hi;
  return (uint32_t)a | ((uint32_t)b << 16);
}

// ------------------------------ RMSNorm + split ----------------------------
__global__ void __launch_bounds__(256) rmsnorm_split_kernel(
    const float* __restrict__ x, const float* __restrict__ g,
    __nv_bfloat16* __restrict__ hh, __nv_bfloat16* __restrict__ hl) {
  int row = blockIdx.x;
  const float4* xr = (const float4*)(x + (size_t)row * DMODEL);
  float4 v0 = xr[threadIdx.x];
  float4 v1 = xr[threadIdx.x + 256];
  float ss = v0.x * v0.x + v0.y * v0.y + v0.z * v0.z + v0.w * v0.w
           + v1.x * v1.x + v1.y * v1.y + v1.z * v1.z + v1.w * v1.w;
  #pragma unroll
  for (int off = 16; off; off >>= 1) ss += __shfl_xor_sync(0xffffffffu, ss, off);
  __shared__ float warpsum[8];
  __shared__ float s_inv;
  if ((threadIdx.x & 31) == 0) warpsum[threadIdx.x >> 5] = ss;
  __syncthreads();
  if (threadIdx.x == 0) {
    float t = 0.f;
    #pragma unroll
    for (int i = 0; i < 8; i++) t += warpsum[i];
    s_inv = rsqrtf(t / (float)DMODEL + 1e-9f);
  }
  __syncthreads();
  float inv = s_inv;
  const float4* gg = (const float4*)g;
  float4 g0 = gg[threadIdx.x];
  float4 g1 = gg[threadIdx.x + 256];
  size_t b0 = (size_t)row * DMODEL + threadIdx.x * 4;
  size_t b1 = (size_t)row * DMODEL + (threadIdx.x + 256) * 4;
  float a0[4] = {v0.x * inv * g0.x, v0.y * inv * g0.y, v0.z * inv * g0.z, v0.w * inv * g0.w};
  float a1[4] = {v1.x * inv * g1.x, v1.y * inv * g1.y, v1.z * inv * g1.z, v1.w * inv * g1.w};
  #pragma unroll
  for (int c = 0; c < 4; c++) {
    __nv_bfloat16 hi0 = __float2bfloat16(a0[c]);
    hh[b0 + c] = hi0;
    hl[b0 + c] = __float2bfloat16(a0[c] - __bfloat162float(hi0));
    __nv_bfloat16 hi1 = __float2bfloat16(a1[c]);
    hh[b1 + c] = hi1;
    hl[b1 + c] = __float2bfloat16(a1[c] - __bfloat162float(hi1));
  }
}

// -------------- all 4 weight transposes + splits in ONE launch -------------
// Segments over blockIdx.x: wq 4096 | wk 1024 | wv 1024 | wo 4096 tiles.
__global__ void __launch_bounds__(256) transpose_all_kernel(
    const float* __restrict__ wq, const float* __restrict__ wk,
    const float* __restrict__ wv, const float* __restrict__ wo,
    __nv_bfloat16* __restrict__ wqh, __nv_bfloat16* __restrict__ wql,
    __nv_bfloat16* __restrict__ wkh, __nv_bfloat16* __restrict__ wkl,
    __nv_bfloat16* __restrict__ wvh, __nv_bfloat16* __restrict__ wvl,
    __nv_bfloat16* __restrict__ woh, __nv_bfloat16* __restrict__ wol) {
  int b = blockIdx.x;
  const float* w;
  __nv_bfloat16 *th, *tl;
  int N, tile;
  const int K = DMODEL;
  if (b < 4096)      { w = wq; th = wqh; tl = wql; N = DMODEL; tile = b; }
  else if (b < 5120) { w = wk; th = wkh; tl = wkl; N = KVDIM;  tile = b - 4096; }
  else if (b < 6144) { w = wv; th = wvh; tl = wvl; N = KVDIM;  tile = b - 5120; }
  else               { w = wo; th = woh; tl = wol; N = DMODEL; tile = b - 6144; }
  int ntn = N >> 5;
  int n0 = (tile % ntn) * 32;
  int k0 = (tile / ntn) * 32;

  __shared__ float t[32][33];
  int tx = threadIdx.x & 31, ty = threadIdx.x >> 5;
  #pragma unroll
  for (int j = ty; j < 32; j += 8)
    t[j][tx] = w[(size_t)(k0 + j) * N + n0 + tx];
  __syncthreads();

  // write: thread -> (n-row j, 4 consecutive k), vectorized 8B stores
  int j = threadIdx.x >> 3;
  int cg = threadIdx.x & 7;
  float v0 = t[cg * 4 + 0][j], v1 = t[cg * 4 + 1][j];
  float v2 = t[cg * 4 + 2][j], v3 = t[cg * 4 + 3][j];
  __nv_bfloat16 h0 = __float2bfloat16(v0), h1 = __float2bfloat16(v1);
  __nv_bfloat16 h2 = __float2bfloat16(v2), h3 = __float2bfloat16(v3);
  size_t o = (size_t)(n0 + j) * K + k0 + cg * 4;
  *(uint2*)(th + o) = make_uint2(pack2bf(h0, h1), pack2bf(h2, h3));
  *(uint2*)(tl + o) = make_uint2(
      pack2bf(__float2bfloat16(v0 - __bfloat162float(h0)),
              __float2bfloat16(v1 - __bfloat162float(h1))),
      pack2bf(__float2bfloat16(v2 - __bfloat162float(h2)),
              __float2bfloat16(v3 - __bfloat162float(h3))));
}

// ----------------------- HMMA bf16x3 GEMM ----------------------------------
#define MM_STAGE_BYTES 65536
#define MM_SMEM_BYTES  (2 * MM_STAGE_BYTES + 1024)

__global__ void __launch_bounds__(256) mm_kernel(
    const __nv_bfloat16* __restrict__ Ah, const __nv_bfloat16* __restrict__ Al,
    const float* __restrict__ resid, int K,
    const __nv_bfloat16* B0h, const __nv_bfloat16* B0l, float* C0, int N0, int nb0,
    const __nv_bfloat16* B1h, const __nv_bfloat16* B1l, float* C1, int N1, int nb1,
    const __nv_bfloat16* B2h, const __nv_bfloat16* B2l, float* C2, int N2) {
  extern __shared__ char smem_raw[];
  uint32_t sb = smem_u32(smem_raw);
  uint32_t base = (sb + 1023) & ~1023u;

  int tid = threadIdx.x, lane = tid & 31, wid = tid >> 5;
  int wm = wid >> 2;
  int wn = wid & 3;

  const __nv_bfloat16 *Bh, *Bl;
  float* C;
  int N, bn;
  int bxx = blockIdx.x;
  if (bxx < nb0)                { Bh = B0h; Bl = B0l; C = C0; N = N0; bn = bxx * 128; }
  else if (bxx < nb0 + nb1)     { Bh = B1h; Bl = B1l; C = C1; N = N1; bn = (bxx - nb0) * 128; }
  else                          { Bh = B2h; Bl = B2l; C = C2; N = N2; bn = (bxx - nb0 - nb1) * 128; }
  int bm = blockIdx.y * 128;

  float acc[4][4][4];
  #pragma unroll
  for (int i = 0; i < 4; i++)
    #pragma unroll
    for (int j = 0; j < 4; j++)
      #pragma unroll
      for (int r = 0; r < 4; r++) acc[i][j][r] = 0.f;

  int l_row[4], l_ck[4];
  uint32_t l_so[4];
  #pragma unroll
  for (int i = 0; i < 4; i++) {
    int idx = i * 256 + tid;
    l_row[i] = idx >> 3;
    l_ck[i]  = idx & 7;
    l_so[i]  = SWZ128((uint32_t)(l_row[i] * 128 + l_ck[i] * 16));
  }

  const int nch = K >> 6;
  auto stage_base = [&](int s) { return base + (uint32_t)s * MM_STAGE_BYTES; };

  #define MM_LOAD(s, k0_)                                                      \
    do {                                                                       \
      uint32_t stb = stage_base(s);                                            \
      _Pragma("unroll")                                                        \
      for (int i = 0; i < 4; i++) {                                            \
        size_t ga = (size_t)(bm + l_row[i]) * K + (k0_) + l_ck[i] * 8;         \
        size_t gb = (size_t)(bn + l_row[i]) * K + (k0_) + l_ck[i] * 8;         \
        CP_ASYNC16(stb + l_so[i],         Ah + ga);                            \
        CP_ASYNC16(stb + 16384 + l_so[i], Al + ga);                            \
        CP_ASYNC16(stb + 32768 + l_so[i], Bh + gb);                            \
        CP_ASYNC16(stb + 49152 + l_so[i], Bl + gb);                            \
      }                                                                        \
    } while (0)

  MM_LOAD(0, 0);
  CP_COMMIT();

  int a_r = lane & 15;
  int a_k = lane >> 4;
  // X4 B geometry: lanes 0-15 -> n8 tile 2*ntp (two k halves),
  //                lanes 16-31 -> n8 tile 2*ntp+1
  int b_row8 = ((lane >> 4) << 3) + (lane & 7);
  int b_k = (lane >> 3) & 1;

  for (int ch = 0; ch < nch; ch++) {
    if (ch + 1 < nch) {
      MM_LOAD((ch + 1) & 1, (ch + 1) * 64);
      CP_COMMIT();
      CP_WAIT1();
    } else {
      CP_WAIT0();
    }
    __syncthreads();

    uint32_t stb = stage_base(ch & 1);
    #pragma unroll
    for (int ks = 0; ks < 4; ks++) {
      uint32_t fa_h[4][4], fa_l[4][4], fb_h[2][4], fb_l[2][4];
      #pragma unroll
      for (int mt = 0; mt < 4; mt++) {
        uint32_t off = SWZ128((uint32_t)((wm * 64 + mt * 16 + a_r) * 128 +
                                         (ks * 2 + a_k) * 16));
        LDSM_X4(fa_h[mt][0], fa_h[mt][1], fa_h[mt][2], fa_h[mt][3], stb + off);
        LDSM_X4(fa_l[mt][0], fa_l[mt][1], fa_l[mt][2], fa_l[mt][3],
                stb + 16384 + off);
      }
      #pragma unroll
      for (int ntp = 0; ntp < 2; ntp++) {
        uint32_t off = SWZ128((uint32_t)((wn * 32 + ntp * 16 + b_row8) * 128 +
                                         (ks * 2 + b_k) * 16));
        LDSM_X4(fb_h[ntp][0], fb_h[ntp][1], fb_h[ntp][2], fb_h[ntp][3],
                stb + 32768 + off);
        LDSM_X4(fb_l[ntp][0], fb_l[ntp][1], fb_l[ntp][2], fb_l[ntp][3],
                stb + 49152 + off);
      }
      #pragma unroll
      for (int mt = 0; mt < 4; mt++)
        #pragma unroll
        for (int ntp = 0; ntp < 2; ntp++)
          #pragma unroll
          for (int half = 0; half < 2; half++) {
            MMA16816(acc[mt][ntp * 2 + half], fa_h[mt], &fb_h[ntp][half * 2]);
            MMA16816(acc[mt][ntp * 2 + half], fa_l[mt], &fb_h[ntp][half * 2]);
            MMA16816(acc[mt][ntp * 2 + half], fa_h[mt], &fb_l[ntp][half * 2]);
          }
    }
    __syncthreads();
  }

  #pragma unroll
  for (int mt = 0; mt < 4; mt++)
    #pragma unroll
    for (int nt = 0; nt < 4; nt++) {
      int r0 = bm + wm * 64 + mt * 16 + (lane >> 2);
      int c0 = bn + wn * 32 + nt * 8 + (lane & 3) * 2;
      float2 v01 = make_float2(acc[mt][nt][0], acc[mt][nt][1]);
      float2 v23 = make_float2(acc[mt][nt][2], acc[mt][nt][3]);
      size_t o0 = (size_t)r0 * N + c0;
      size_t o1 = (size_t)(r0 + 8) * N + c0;
      if (resid) {
        float2 rv0 = *(const float2*)(resid + o0);
        float2 rv1 = *(const float2*)(resid + o1);
        v01.x += rv0.x; v01.y += rv0.y;
        v23.x += rv1.x; v23.y += rv1.y;
      }
      *(float2*)(C + o0) = v01;
      *(float2*)(C + o1) = v23;
    }
}

// ------------------- RoPE + bf16 hi/lo split (k only) ----------------------
__global__ void rope_split_kernel(const float* __restrict__ src,
                                  __nv_bfloat16* __restrict__ hi,
                                  __nv_bfloat16* __restrict__ lo,
                                  int H, float scale, int total) {
  int idx = blockIdx.x * blockDim.x + threadIdx.x;
  if (idx >= total) return;
  int j = idx & 31;
  int tmp = idx >> 5;
  int hh = tmp % H;
  int s = tmp / H;
  float e = (2.0f * (float)j) / 64.0f;
  float inv_freq = powf(10000.0f, -e);
  float ang = (float)s * inv_freq;
  float c, sn;
  sincosf(ang, &sn, &c);
  size_t base = ((size_t)s * H + hh) * HD;
  float x1 = src[base + j];
  float x2 = src[base + j + 32];
  float y1 = (x1 * c - x2 * sn) * scale;
  float y2 = (x1 * sn + x2 * c) * scale;
  __nv_bfloat16 h1 = __float2bfloat16(y1);
  hi[base + j] = h1;
  lo[base + j] = __float2bfloat16(y1 - __bfloat162float(h1));
  __nv_bfloat16 h2 = __float2bfloat16(y2);
  hi[base + j + 32] = h2;
  lo[base + j + 32] = __float2bfloat16(y2 - __bfloat162float(h2));
}

// ------------- V split + transpose: [S][8][64] -> [8][64][S] bf16 ----------
__global__ void __launch_bounds__(256) split_vT_kernel(
    const float* __restrict__ v, __nv_bfloat16* __restrict__ th,
    __nv_bfloat16* __restrict__ tl) {
  __shared__ float t[32][33];
  int s0 = blockIdx.x * 32, d0 = blockIdx.y * 32, h = blockIdx.z;
  int tx = threadIdx.x & 31, ty = threadIdx.x >> 5;
  #pragma unroll
  for (int j = ty; j < 32; j += 8)
    t[j][tx] = v[((size_t)(s0 + j) * HKV + h) * HD + d0 + tx];
  __syncthreads();
  int j = threadIdx.x >> 3;
  int cg = threadIdx.x & 7;
  float v0 = t[cg * 4 + 0][j], v1 = t[cg * 4 + 1][j];
  float v2 = t[cg * 4 + 2][j], v3 = t[cg * 4 + 3][j];
  __nv_bfloat16 h0 = __float2bfloat16(v0), h1 = __float2bfloat16(v1);
  __nv_bfloat16 h2 = __float2bfloat16(v2), h3 = __float2bfloat16(v3);
  size_t o = ((size_t)h * HD + d0 + j) * S_LEN + s0 + cg * 4;
  *(uint2*)(th + o) = make_uint2(pack2bf(h0, h1), pack2bf(h2, h3));
  *(uint2*)(tl + o) = make_uint2(
      pack2bf(__float2bfloat16(v0 - __bfloat162float(h0)),
              __float2bfloat16(v1 - __bfloat162float(h1))),
      pack2bf(__float2bfloat16(v2 - __bfloat162float(h2)),
              __float2bfloat16(v3 - __bfloat162float(h3))));
}

// --------------------- Flash attention on HMMA -----------------------------
// CTA: (head, 64-q-row tile). 4 warps x 16 rows. K/V 64x64 tiles, 2 stages.
// smem: Qh@0(8K), Ql@8K(8K), Qf fp32 staging @16K (64x68 floats), stages@34K.
#define FL_QF_OFF   16384
#define FL_QF_STRIDE 68            // floats per row (pad to kill bank conflicts)
#define FL_ST_OFF   34816
#define FLASH_SMEM  (FL_ST_OFF + 2 * 32768 + 1024)

__global__ void __launch_bounds__(128) flash_hmma_kernel(
    const float* __restrict__ qsrc,
    const __nv_bfloat16* __restrict__ kh, const __nv_bfloat16* __restrict__ kl,
    const __nv_bfloat16* __restrict__ vth, const __nv_bfloat16* __restrict__ vtl,
    __nv_bfloat16* __restrict__ Ohi, __nv_bfloat16* __restrict__ Olo) {
  extern __shared__ char smem_raw[];
  uint32_t sb = smem_u32(smem_raw);
  uint32_t base = (sb + 1023) & ~1023u;
  char* smem = smem_raw + (base - sb);

  int tid = threadIdx.x, lane = tid & 31, wid = tid >> 5;
  int h = blockIdx.x;
  int qt = gridDim.y - 1 - blockIdx.y;     // heavy tiles first
  int hk = h >> 2;
  int q0 = qt * 64;

  // ---- Q fp32 tile -> smem staging (group 0) ------------------------------
  #pragma unroll
  for (int i = 0; i < 8; i++) {
    int idx = i * 128 + tid;
    int row = idx >> 4, ck = idx & 15;     // 64 rows x 16 chunks(16B)
    uint32_t dst = base + FL_QF_OFF + row * (FL_QF_STRIDE * 4) + ck * 16;
    CP_ASYNC16(dst, qsrc + ((size_t)(q0 + row) * HQ + h) * HD + ck * 4);
  }
  CP_COMMIT();

  #define FL_LOAD(s, k0_)                                                     \
    do {                                                                      \
      uint32_t stb = base + FL_ST_OFF + (uint32_t)(s) * 32768;                \
      _Pragma("unroll")                                                       \
      for (int i = 0; i < 4; i++) {                                           \
        int idx = i * 128 + tid;                                              \
        int row = idx >> 3, ck = idx & 7;                                     \
        uint32_t so = SWZ128((uint32_t)(row * 128 + ck * 16));                \
        size_t gk = ((size_t)((k0_) + row) * HKV + hk) * HD + ck * 8;         \
        size_t gv = ((size_t)hk * HD + row) * S_LEN + (k0_) + ck * 8;         \
        CP_ASYNC16(stb + so, kh + gk);                                        \
        CP_ASYNC16(stb + 8192 + so, kl + gk);                                 \
        CP_ASYNC16(stb + 16384 + so, vth + gv);                               \
        CP_ASYNC16(stb + 24576 + so, vtl + gv);                               \
      }                                                                       \
    } while (0)

  FL_LOAD(0, 0);
  CP_COMMIT();

  // ---- fused RoPE + split on Q (once per CTA) -----------------------------
  CP_WAIT1();                 // Q staging done (stage 0 may still be in flight)
  __syncthreads();
  {
    const float* Qf = (const float*)(smem + FL_QF_OFF);
    int row = tid >> 1;
    int jb = (tid & 1) * 16;
    float pos = (float)(q0 + row);
    #pragma unroll
    for (int jj = 0; jj < 16; jj++) {
      int j = jb + jj;
      float e = (2.0f * (float)j) / 64.0f;
      float inv_freq = powf(10000.0f, -e);
      float c, sn;
      sincosf(pos * inv_freq, &sn, &c);
      float x1 = Qf[row * FL_QF_STRIDE + j];
      float x2 = Qf[row * FL_QF_STRIDE + j + 32];
      float y1 = (x1 * c - x2 * sn) * 0.125f;
      float y2 = (x1 * sn + x2 * c) * 0.125f;
      __nv_bfloat16 h1 = __float2bfloat16(y1);
      __nv_bfloat16 h2 = __float2bfloat16(y2);
      uint32_t so1 = SWZ128((uint32_t)(row * 128 + j * 2));
      uint32_t so2 = SWZ128((uint32_t)(row * 128 + (j + 32) * 2));
      *(__nv_bfloat16*)(smem + so1) = h1;
      *(__nv_bfloat16*)(smem + so2) = h2;
      *(__nv_bfloat16*)(smem + 8192 + so1) =
          __float2bfloat16(y1 - __bfloat162float(h1));
      *(__nv_bfloat16*)(smem + 8192 + so2) =
          __float2bfloat16(y2 - __bfloat162float(h2));
    }
  }

  int a_r = lane & 15, a_k = lane >> 4;
  int b_row8 = ((lane >> 4) << 3) + (lane & 7);   // X4: row within 16-row pair
  int b_k = (lane >> 3) & 1;
  int r_in8 = lane >> 2;
  int c2 = (lane & 3) * 2;

  uint32_t qfh[4][4], qfl[4][4];
  float oacc[8][4];
  #pragma unroll
  for (int i = 0; i < 8; i++)
    #pragma unroll
    for (int j = 0; j < 4; j++) oacc[i][j] = 0.f;
  const float NEG_INF = __int_as_float(0xff800000);
  float m0 = NEG_INF, m1 = NEG_INF, l0 = 0.f, l1 = 0.f;

  for (int kt = 0; kt <= qt; kt++) {
    if (kt + 1 <= qt) {
      FL_LOAD((kt + 1) & 1, (kt + 1) * 64);
      CP_COMMIT();
      CP_WAIT1();
    } else {
      CP_WAIT0();
    }
    __syncthreads();
    uint32_t stb = base + FL_ST_OFF + (uint32_t)(kt & 1) * 32768;

    if (kt == 0) {   // Q fragments once (rope writes visible after barrier)
      #pragma unroll
      for (int ks = 0; ks < 4; ks++) {
        uint32_t off = SWZ128((uint32_t)((wid * 16 + a_r) * 128 +
                                         (ks * 2 + a_k) * 16));
        LDSM_X4(qfh[ks][0], qfh[ks][1], qfh[ks][2], qfh[ks][3], base + off);
        LDSM_X4(qfl[ks][0], qfl[ks][1], qfl[ks][2], qfl[ks][3],
                base + 8192 + off);
      }
    }

    // ---- S = Q K^T (x3 split), 16x64 per warp; X4 B-frags -----------------
    float sacc[8][4];
    #pragma unroll
    for (int i = 0; i < 8; i++)
      #pragma unroll
      for (int j = 0; j < 4; j++) sacc[i][j] = 0.f;

    #pragma unroll
    for (int ks = 0; ks < 4; ks++)
      #pragma unroll
      for (int ntp = 0; ntp < 4; ntp++) {
        uint32_t off = SWZ128((uint32_t)((ntp * 16 + b_row8) * 128 +
                                         (ks * 2 + b_k) * 16));
        uint32_t kbh[4], kbl[4];
        LDSM_X4(kbh[0], kbh[1], kbh[2], kbh[3], stb + off);
        LDSM_X4(kbl[0], kbl[1], kbl[2], kbl[3], stb + 8192 + off);
        MMA16816(sacc[ntp * 2], qfh[ks], &kbh[0]);
        MMA16816(sacc[ntp * 2], qfl[ks], &kbh[0]);
        MMA16816(sacc[ntp * 2], qfh[ks], &kbl[0]);
        MMA16816(sacc[ntp * 2 + 1], qfh[ks], &kbh[2]);
        MMA16816(sacc[ntp * 2 + 1], qfl[ks], &kbh[2]);
        MMA16816(sacc[ntp * 2 + 1], qfh[ks], &kbl[2]);
      }

    int r0 = q0 + wid * 16 + r_in8;
    int r1 = r0 + 8;
    if (kt == qt) {    // causal mask on diagonal tile
      #pragma unroll
      for (int nt = 0; nt < 8; nt++) {
        int cg = kt * 64 + nt * 8 + c2;
        if (cg > r0)     sacc[nt][0] = NEG_INF;
        if (cg + 1 > r0) sacc[nt][1] = NEG_INF;
        if (cg > r1)     sacc[nt][2] = NEG_INF;
        if (cg + 1 > r1) sacc[nt][3] = NEG_INF;
      }
    }

    // ---- online softmax ---------------------------------------------------
    float mx0 = m0, mx1 = m1;
    #pragma unroll
    for (int nt = 0; nt < 8; nt++) {
      mx0 = fmaxf(mx0, fmaxf(sacc[nt][0], sacc[nt][1]));
      mx1 = fmaxf(mx1, fmaxf(sacc[nt][2], sacc[nt][3]));
    }
    mx0 = fmaxf(mx0, __shfl_xor_sync(0xffffffffu, mx0, 1));
    mx0 = fmaxf(mx0, __shfl_xor_sync(0xffffffffu, mx0, 2));
    mx1 = fmaxf(mx1, __shfl_xor_sync(0xffffffffu, mx1, 1));
    mx1 = fmaxf(mx1, __shfl_xor_sync(0xffffffffu, mx1, 2));
    float sc0 = __expf(m0 - mx0), sc1 = __expf(m1 - mx1);
    m0 = mx0; m1 = mx1;

    uint32_t pAh[16], pAl[16];
    float rs0 = 0.f, rs1 = 0.f;
    #pragma unroll
    for (int nt = 0; nt < 8; nt++) {
      float p0 = __expf(sacc[nt][0] - m0);
      float p1 = __expf(sacc[nt][1] - m0);
      float p2 = __expf(sacc[nt][2] - m1);
      float p3 = __expf(sacc[nt][3] - m1);
      rs0 += p0 + p1;
      rs1 += p2 + p3;
      __nv_bfloat16 b0 = __float2bfloat16(p0), b1 = __float2bfloat16(p1);
      __nv_bfloat16 b2 = __float2bfloat16(p2), b3 = __float2bfloat16(p3);
      pAh[nt * 2]     = pack2bf(b0, b1);
      pAh[nt * 2 + 1] = pack2bf(b2, b3);
      pAl[nt * 2]     = pack2bf(__float2bfloat16(p0 - __bfloat162float(b0)),
                                __float2bfloat16(p1 - __bfloat162float(b1)));
      pAl[nt * 2 + 1] = pack2bf(__float2bfloat16(p2 - __bfloat162float(b2)),
                                __float2bfloat16(p3 - __bfloat162float(b3)));
    }
    rs0 += __shfl_xor_sync(0xffffffffu, rs0, 1);
    rs0 += __shfl_xor_sync(0xffffffffu, rs0, 2);
    rs1 += __shfl_xor_sync(0xffffffffu, rs1, 1);
    rs1 += __shfl_xor_sync(0xffffffffu, rs1, 2);
    l0 = l0 * sc0 + rs0;
    l1 = l1 * sc1 + rs1;
    #pragma unroll
    for (int nt = 0; nt < 8; nt++) {
      oacc[nt][0] *= sc0; oacc[nt][1] *= sc0;
      oacc[nt][2] *= sc1; oacc[nt][3] *= sc1;
    }

    // ---- O += P V (x3 split); X4 V B-frags --------------------------------
    #pragma unroll
    for (int ksp = 0; ksp < 4; ksp++)
      #pragma unroll
      for (int ntp = 0; ntp < 4; ntp++) {
        uint32_t off = SWZ128((uint32_t)((ntp * 16 + b_row8) * 128 +
                                         (ksp * 2 + b_k) * 16));
        uint32_t vbh[4], vbl[4];
        LDSM_X4(vbh[0], vbh[1], vbh[2], vbh[3], stb + 16384 + off);
        LDSM_X4(vbl[0], vbl[1], vbl[2], vbl[3], stb + 24576 + off);
        MMA16816(oacc[ntp * 2], &pAh[4 * ksp], &vbh[0]);
        MMA16816(oacc[ntp * 2], &pAl[4 * ksp], &vbh[0]);
        MMA16816(oacc[ntp * 2], &pAh[4 * ksp], &vbl[0]);
        MMA16816(oacc[ntp * 2 + 1], &pAh[4 * ksp], &vbh[2]);
        MMA16816(oacc[ntp * 2 + 1], &pAl[4 * ksp], &vbh[2]);
        MMA16816(oacc[ntp * 2 + 1], &pAh[4 * ksp], &vbl[2]);
      }
    __syncthreads();
  }

  // ---- epilogue: normalize, split to bf16 hi/lo, store --------------------
  float inv0 = 1.f / l0, inv1 = 1.f / l1;
  int r0 = q0 + wid * 16 + r_in8;
  #pragma unroll
  for (int ntd = 0; ntd < 8; ntd++) {
    int col = h * HD + ntd * 8 + c2;
    float v00 = oacc[ntd][0] * inv0, v01 = oacc[ntd][1] * inv0;
    float v10 = oacc[ntd][2] * inv1, v11 = oacc[ntd][3] * inv1;
    __nv_bfloat16 h00 = __float2bfloat16(v00), h01 = __float2bfloat16(v01);
    __nv_bfloat16 h10 = __float2bfloat16(v10), h11 = __float2bfloat16(v11);
    size_t o0 = (size_t)r0 * DMODEL + col;
    size_t o1 = (size_t)(r0 + 8) * DMODEL + col;
    *(uint32_t*)(Ohi + o0) = pack2bf(h00, h01);
    *(uint32_t*)(Ohi + o1) = pack2bf(h10, h11);
    *(uint32_t*)(Olo + o0) =
        pack2bf(__float2bfloat16(v00 - __bfloat162float(h00)),
                __float2bfloat16(v01 - __bfloat162float(h01)));
    *(uint32_t*)(Olo + o1) =
        pack2bf(__float2bfloat16(v10 - __bfloat162float(h10)),
                __float2bfloat16(v11 - __bfloat162float(h11)));
  }
}

// ------------------------------ launch -------------------------------------
extern "C" void kernel_launch(void* const* d_in, const int* in_sizes, int n_in,
                              void* d_out, int out_size) {
  const float* x  = (const float*)d_in[0];
  const float* g  = (const float*)d_in[1];
  const float* wq = (const float*)d_in[2];
  const float* wk = (const float*)d_in[3];
  const float* wv = (const float*)d_in[4];
  const float* wo = (const float*)d_in[5];
  float* out = (float*)d_out;

  __nv_bfloat16 *hh, *hl, *wqh, *wql, *wkh, *wkl, *wvh, *wvl, *woh, *wol;
  __nv_bfloat16 *ohi, *olo, *khp, *klp, *vth, *vtl;
  float *q, *k, *v;
  cudaGetSymbolAddress((void**)&hh, g_h_hi);
  cudaGetSymbolAddress((void**)&hl, g_h_lo);
  cudaGetSymbolAddress((void**)&wqh, g_wqT_hi);
  cudaGetSymbolAddress((void**)&wql, g_wqT_lo);
  cudaGetSymbolAddress((void**)&wkh, g_wkT_hi);
  cudaGetSymbolAddress((void**)&wkl, g_wkT_lo);
  cudaGetSymbolAddress((void**)&wvh, g_wvT_hi);
  cudaGetSymbolAddress((void**)&wvl, g_wvT_lo);
  cudaGetSymbolAddress((void**)&woh, g_woT_hi);
  cudaGetSymbolAddress((void**)&wol, g_woT_lo);
  cudaGetSymbolAddress((void**)&ohi, g_o_hi);
  cudaGetSymbolAddress((void**)&olo, g_o_lo);
  cudaGetSymbolAddress((void**)&khp, g_kh);
  cudaGetSymbolAddress((void**)&klp, g_kl);
  cudaGetSymbolAddress((void**)&vth, g_vth);
  cudaGetSymbolAddress((void**)&vtl, g_vtl);
  cudaGetSymbolAddress((void**)&q, g_q);
  cudaGetSymbolAddress((void**)&k, g_k);
  cudaGetSymbolAddress((void**)&v, g_v);

  cudaFuncSetAttribute(mm_kernel, cudaFuncAttributeMaxDynamicSharedMemorySize,
                       MM_SMEM_BYTES);
  cudaFuncSetAttribute(flash_hmma_kernel,
                       cudaFuncAttributeMaxDynamicSharedMemorySize, FLASH_SMEM);

  // all weight transposes + bf16 hi/lo splits (one launch)
  transpose_all_kernel<<<10240, 256>>>(wq, wk, wv, wo, wqh, wql, wkh, wkl,
                                       wvh, wvl, woh, wol);

  // rmsnorm + split
  rmsnorm_split_kernel<<<S_LEN, 256>>>(x, g, hh, hl);

  // q/k/v projections (one fused HMMA launch: 16|4|4 column segments)
  mm_kernel<<<dim3(24, S_LEN / 128), 256, MM_SMEM_BYTES>>>(
      hh, hl, nullptr, DMODEL,
      wqh, wql, q, DMODEL, 16,
      wkh, wkl, k, KVDIM, 4,
      wvh, wvl, v, KVDIM);

  // rope + split for k; v split+transpose (q rope is fused into flash)
  {
    int totk = S_LEN * HKV * 32;
    rope_split_kernel<<<(totk + 255) / 256, 256>>>(k, khp, klp, HKV, 1.0f, totk);
    split_vT_kernel<<<dim3(S_LEN / 32, HD / 32, HKV), 256>>>(v, vth, vtl);
  }

  // causal flash attention on HMMA (GQA); ropes+splits Q in-kernel
  flash_hmma_kernel<<<dim3(HQ, S_LEN / 64), 128, FLASH_SMEM>>>(
      q, khp, klp, vth, vtl, ohi, olo);

  // output projection + residual
  mm_kernel<<<dim3(16, S_LEN / 128), 256, MM_SMEM_BYTES>>>(
      ohi, olo, x, DMODEL,
      woh, wol, out, DMODEL, 16,
      nullptr, nullptr, nullptr, 0, 0,
      nullptr, nullptr, nullptr, 0);
}

// round 16
// speedup vs baseline: 1.4888x; 1.4888x over previous
#include <cuda_runtime.h>
#include <cuda_bf16.h>
#include <stdint.h>
#include <math.h>

// ---------------------------------------------------------------------------
// GQAWithKVCache — round 14: revert to R13-best tensor kernels (mm X2 ldsm,
// flash X2 ldsm, precomputed Q rope) + safe pointwise fusions only:
//   - all 4 weight transposes fused into one vectorized launch
//   - vectorized split_vT stores
// Shapes: B=1, S=2048, D_MODEL=2048, HQ=32, HKV=8, HD=64.
// ---------------------------------------------------------------------------

#define S_LEN   2048
#define DMODEL  2048
#define HQ      32
#define HKV     8
#define HD      64
#define KVDIM   (HKV * HD)   // 512

// ------------------------- scratch (no allocations) ------------------------
__device__ __align__(16) __nv_bfloat16 g_h_hi[S_LEN * DMODEL];
__device__ __align__(16) __nv_bfloat16 g_h_lo[S_LEN * DMODEL];
__device__ __align__(16) __nv_bfloat16 g_wqT_hi[DMODEL * DMODEL];  // [N][K]
__device__ __align__(16) __nv_bfloat16 g_wqT_lo[DMODEL * DMODEL];
__device__ __align__(16) __nv_bfloat16 g_wkT_hi[KVDIM * DMODEL];
__device__ __align__(16) __nv_bfloat16 g_wkT_lo[KVDIM * DMODEL];
__device__ __align__(16) __nv_bfloat16 g_wvT_hi[KVDIM * DMODEL];
__device__ __align__(16) __nv_bfloat16 g_wvT_lo[KVDIM * DMODEL];
__device__ __align__(16) __nv_bfloat16 g_woT_hi[DMODEL * DMODEL];
__device__ __align__(16) __nv_bfloat16 g_woT_lo[DMODEL * DMODEL];
__device__ __align__(16) __nv_bfloat16 g_o_hi[S_LEN * DMODEL];
__device__ __align__(16) __nv_bfloat16 g_o_lo[S_LEN * DMODEL];
__device__ float g_q[S_LEN * DMODEL];
__device__ float g_k[S_LEN * KVDIM];
__device__ float g_v[S_LEN * KVDIM];
// bf16 split operands for flash
__device__ __align__(16) __nv_bfloat16 g_qh[S_LEN * DMODEL];   // roped, *0.125
__device__ __align__(16) __nv_bfloat16 g_ql[S_LEN * DMODEL];
__device__ __align__(16) __nv_bfloat16 g_kh[S_LEN * KVDIM];    // roped
__device__ __align__(16) __nv_bfloat16 g_kl[S_LEN * KVDIM];
__device__ __align__(16) __nv_bfloat16 g_vth[KVDIM * S_LEN];   // [h][d][s]
__device__ __align__(16) __nv_bfloat16 g_vtl[KVDIM * S_LEN];

// ------------------------------ PTX helpers --------------------------------
__device__ __forceinline__ uint32_t smem_u32(const void* p) {
  uint32_t a;
  asm("{ .reg .u64 t; cvta.to.shared.u64 t, %1; cvt.u32.u64 %0, t; }"
      : "=r"(a) : "l"(p));
  return a;
}

#define SWZ128(x) ((x) ^ (((x) >> 3) & 0x70))

#define CP_ASYNC16(dst, src) \
  asm volatile("cp.async.cg.shared.global [%0], [%1], 16;" \
               :: "r"(dst), "l"(src) : "memory")
#define CP_COMMIT() asm volatile("cp.async.commit_group;" ::: "memory")
#define CP_WAIT0()  asm volatile("cp.async.wait_group 0;" ::: "memory")
#define CP_WAIT1()  asm volatile("cp.async.wait_group 1;" ::: "memory")

#define LDSM_X4(r0, r1, r2, r3, addr)                                     \
  asm volatile("ldmatrix.sync.aligned.m8n8.x4.shared.b16 {%0,%1,%2,%3}, [%4];" \
               : "=r"(r0), "=r"(r1), "=r"(r2), "=r"(r3) : "r"(addr))
#define LDSM_X2(r0, r1, addr)                                             \
  asm volatile("ldmatrix.sync.aligned.m8n8.x2.shared.b16 {%0,%1}, [%2];"  \
               : "=r"(r0), "=r"(r1) : "r"(addr))

#define MMA16816(c, a, b)                                                 \
  asm volatile(                                                           \
      "mma.sync.aligned.m16n8k16.row.col.f32.bf16.bf16.f32 "              \
      "{%0,%1,%2,%3},{%4,%5,%6,%7},{%8,%9},{%0,%1,%2,%3};"                \
      : "+f"((c)[0]), "+f"((c)[1]), "+f"((c)[2]), "+f"((c)[3])            \
      : "r"((a)[0]), "r"((a)[1]), "r"((a)[2]), "r"((a)[3]),               \
        "r"((b)[0]), "r"((b)[1]))

__device__ __forceinline__ uint32_t pack2bf(__nv_bfloat16 lo, __nv_bfloat16 hi) {
  uint16_t a = *(uint16_t*)&lo, b = *(uint16_t*)&hi;
  return (uint32_t)a | ((uint32_t)b << 16);
}

// ------------------------------ RMSNorm + split ----------------------------
__global__ void __launch_bounds__(256) rmsnorm_split_kernel(
    const float* __restrict__ x, const float* __restrict__ g,
    __nv_bfloat16* __restrict__ hh, __nv_bfloat16* __restrict__ hl) {
  int row = blockIdx.x;
  const float4* xr = (const float4*)(x + (size_t)row * DMODEL);
  float4 v0 = xr[threadIdx.x];
  float4 v1 = xr[threadIdx.x + 256];
  float ss = v0.x * v0.x + v0.y * v0.y + v0.z * v0.z + v0.w * v0.w
           + v1.x * v1.x + v1.y * v1.y + v1.z * v1.z + v1.w * v1.w;
  #pragma unroll
  for (int off = 16; off; off >>= 1) ss += __shfl_xor_sync(0xffffffffu, ss, off);
  __shared__ float warpsum[8];
  __shared__ float s_inv;
  if ((threadIdx.x & 31) == 0) warpsum[threadIdx.x >> 5] = ss;
  __syncthreads();
  if (threadIdx.x == 0) {
    float t = 0.f;
    #pragma unroll
    for (int i = 0; i < 8; i++) t += warpsum[i];
    s_inv = rsqrtf(t / (float)DMODEL + 1e-9f);
  }
  __syncthreads();
  float inv = s_inv;
  const float4* gg = (const float4*)g;
  float4 g0 = gg[threadIdx.x];
  float4 g1 = gg[threadIdx.x + 256];
  size_t b0 = (size_t)row * DMODEL + threadIdx.x * 4;
  size_t b1 = (size_t)row * DMODEL + (threadIdx.x + 256) * 4;
  float a0[4] = {v0.x * inv * g0.x, v0.y * inv * g0.y, v0.z * inv * g0.z, v0.w * inv * g0.w};
  float a1[4] = {v1.x * inv * g1.x, v1.y * inv * g1.y, v1.z * inv * g1.z, v1.w * inv * g1.w};
  #pragma unroll
  for (int c = 0; c < 4; c++) {
    __nv_bfloat16 hi0 = __float2bfloat16(a0[c]);
    hh[b0 + c] = hi0;
    hl[b0 + c] = __float2bfloat16(a0[c] - __bfloat162float(hi0));
    __nv_bfloat16 hi1 = __float2bfloat16(a1[c]);
    hh[b1 + c] = hi1;
    hl[b1 + c] = __float2bfloat16(a1[c] - __bfloat162float(hi1));
  }
}

// -------------- all 4 weight transposes + splits in ONE launch -------------
// Segments over blockIdx.x: wq 4096 | wk 1024 | wv 1024 | wo 4096 tiles.
__global__ void __launch_bounds__(256) transpose_all_kernel(
    const float* __restrict__ wq, const float* __restrict__ wk,
    const float* __restrict__ wv, const float* __restrict__ wo,
    __nv_bfloat16* __restrict__ wqh, __nv_bfloat16* __restrict__ wql,
    __nv_bfloat16* __restrict__ wkh, __nv_bfloat16* __restrict__ wkl,
    __nv_bfloat16* __restrict__ wvh, __nv_bfloat16* __restrict__ wvl,
    __nv_bfloat16* __restrict__ woh, __nv_bfloat16* __restrict__ wol) {
  int b = blockIdx.x;
  const float* w;
  __nv_bfloat16 *th, *tl;
  int N, tile;
  const int K = DMODEL;
  if (b < 4096)      { w = wq; th = wqh; tl = wql; N = DMODEL; tile = b; }
  else if (b < 5120) { w = wk; th = wkh; tl = wkl; N = KVDIM;  tile = b - 4096; }
  else if (b < 6144) { w = wv; th = wvh; tl = wvl; N = KVDIM;  tile = b - 5120; }
  else               { w = wo; th = woh; tl = wol; N = DMODEL; tile = b - 6144; }
  int ntn = N >> 5;
  int n0 = (tile % ntn) * 32;
  int k0 = (tile / ntn) * 32;

  __shared__ float t[32][33];
  int tx = threadIdx.x & 31, ty = threadIdx.x >> 5;
  #pragma unroll
  for (int j = ty; j < 32; j += 8)
    t[j][tx] = w[(size_t)(k0 + j) * N + n0 + tx];
  __syncthreads();

  // write: thread -> (n-row j, 4 consecutive k), vectorized 8B stores
  int j = threadIdx.x >> 3;
  int cg = threadIdx.x & 7;
  float v0 = t[cg * 4 + 0][j], v1 = t[cg * 4 + 1][j];
  float v2 = t[cg * 4 + 2][j], v3 = t[cg * 4 + 3][j];
  __nv_bfloat16 h0 = __float2bfloat16(v0), h1 = __float2bfloat16(v1);
  __nv_bfloat16 h2 = __float2bfloat16(v2), h3 = __float2bfloat16(v3);
  size_t o = (size_t)(n0 + j) * K + k0 + cg * 4;
  *(uint2*)(th + o) = make_uint2(pack2bf(h0, h1), pack2bf(h2, h3));
  *(uint2*)(tl + o) = make_uint2(
      pack2bf(__float2bfloat16(v0 - __bfloat162float(h0)),
              __float2bfloat16(v1 - __bfloat162float(h1))),
      pack2bf(__float2bfloat16(v2 - __bfloat162float(h2)),
              __float2bfloat16(v3 - __bfloat162float(h3))));
}

// ----------------------- HMMA bf16x3 GEMM (R13-best, X2 B-frags) -----------
#define MM_STAGE_BYTES 65536
#define MM_SMEM_BYTES  (2 * MM_STAGE_BYTES + 1024)

__global__ void __launch_bounds__(256) mm_kernel(
    const __nv_bfloat16* __restrict__ Ah, const __nv_bfloat16* __restrict__ Al,
    const float* __restrict__ resid, int K,
    const __nv_bfloat16* B0h, const __nv_bfloat16* B0l, float* C0, int N0, int nb0,
    const __nv_bfloat16* B1h, const __nv_bfloat16* B1l, float* C1, int N1, int nb1,
    const __nv_bfloat16* B2h, const __nv_bfloat16* B2l, float* C2, int N2) {
  extern __shared__ char smem_raw[];
  uint32_t sb = smem_u32(smem_raw);
  uint32_t base = (sb + 1023) & ~1023u;

  int tid = threadIdx.x, lane = tid & 31, wid = tid >> 5;
  int wm = wid >> 2;
  int wn = wid & 3;

  const __nv_bfloat16 *Bh, *Bl;
  float* C;
  int N, bn;
  int bxx = blockIdx.x;
  if (bxx < nb0)                { Bh = B0h; Bl = B0l; C = C0; N = N0; bn = bxx * 128; }
  else if (bxx < nb0 + nb1)     { Bh = B1h; Bl = B1l; C = C1; N = N1; bn = (bxx - nb0) * 128; }
  else                          { Bh = B2h; Bl = B2l; C = C2; N = N2; bn = (bxx - nb0 - nb1) * 128; }
  int bm = blockIdx.y * 128;

  float acc[4][4][4];
  #pragma unroll
  for (int i = 0; i < 4; i++)
    #pragma unroll
    for (int j = 0; j < 4; j++)
      #pragma unroll
      for (int r = 0; r < 4; r++) acc[i][j][r] = 0.f;

  int l_row[4], l_ck[4];
  uint32_t l_so[4];
  #pragma unroll
  for (int i = 0; i < 4; i++) {
    int idx = i * 256 + tid;
    l_row[i] = idx >> 3;
    l_ck[i]  = idx & 7;
    l_so[i]  = SWZ128((uint32_t)(l_row[i] * 128 + l_ck[i] * 16));
  }

  const int nch = K >> 6;
  auto stage_base = [&](int s) { return base + (uint32_t)s * MM_STAGE_BYTES; };

  #define MM_LOAD(s, k0_)                                                      \
    do {                                                                       \
      uint32_t stb = stage_base(s);                                            \
      _Pragma("unroll")                                                        \
      for (int i = 0; i < 4; i++) {                                            \
        size_t ga = (size_t)(bm + l_row[i]) * K + (k0_) + l_ck[i] * 8;         \
        size_t gb = (size_t)(bn + l_row[i]) * K + (k0_) + l_ck[i] * 8;         \
        CP_ASYNC16(stb + l_so[i],         Ah + ga);                            \
        CP_ASYNC16(stb + 16384 + l_so[i], Al + ga);                            \
        CP_ASYNC16(stb + 32768 + l_so[i], Bh + gb);                            \
        CP_ASYNC16(stb + 49152 + l_so[i], Bl + gb);                            \
      }                                                                        \
    } while (0)

  MM_LOAD(0, 0);
  CP_COMMIT();

  int a_r = lane & 15;
  int a_k = lane >> 4;
  int b_r = lane & 7;
  int b_k = (lane >> 3) & 1;

  for (int ch = 0; ch < nch; ch++) {
    if (ch + 1 < nch) {
      MM_LOAD((ch + 1) & 1, (ch + 1) * 64);
      CP_COMMIT();
      CP_WAIT1();
    } else {
      CP_WAIT0();
    }
    __syncthreads();

    uint32_t stb = stage_base(ch & 1);
    #pragma unroll
    for (int ks = 0; ks < 4; ks++) {
      uint32_t fa_h[4][4], fa_l[4][4], fb_h[4][2], fb_l[4][2];
      #pragma unroll
      for (int mt = 0; mt < 4; mt++) {
        uint32_t off = SWZ128((uint32_t)((wm * 64 + mt * 16 + a_r) * 128 +
                                         (ks * 2 + a_k) * 16));
        LDSM_X4(fa_h[mt][0], fa_h[mt][1], fa_h[mt][2], fa_h[mt][3], stb + off);
        LDSM_X4(fa_l[mt][0], fa_l[mt][1], fa_l[mt][2], fa_l[mt][3],
                stb + 16384 + off);
      }
      #pragma unroll
      for (int nt = 0; nt < 4; nt++) {
        uint32_t off = SWZ128((uint32_t)((wn * 32 + nt * 8 + b_r) * 128 +
                                         (ks * 2 + b_k) * 16));
        LDSM_X2(fb_h[nt][0], fb_h[nt][1], stb + 32768 + off);
        LDSM_X2(fb_l[nt][0], fb_l[nt][1], stb + 49152 + off);
      }
      #pragma unroll
      for (int mt = 0; mt < 4; mt++)
        #pragma unroll
        for (int nt = 0; nt < 4; nt++) {
          MMA16816(acc[mt][nt], fa_h[mt], fb_h[nt]);
          MMA16816(acc[mt][nt], fa_l[mt], fb_h[nt]);
          MMA16816(acc[mt][nt], fa_h[mt], fb_l[nt]);
        }
    }
    __syncthreads();
  }

  #pragma unroll
  for (int mt = 0; mt < 4; mt++)
    #pragma unroll
    for (int nt = 0; nt < 4; nt++) {
      int r0 = bm + wm * 64 + mt * 16 + (lane >> 2);
      int c0 = bn + wn * 32 + nt * 8 + (lane & 3) * 2;
      float2 v01 = make_float2(acc[mt][nt][0], acc[mt][nt][1]);
      float2 v23 = make_float2(acc[mt][nt][2], acc[mt][nt][3]);
      size_t o0 = (size_t)r0 * N + c0;
      size_t o1 = (size_t)(r0 + 8) * N + c0;
      if (resid) {
        float2 rv0 = *(const float2*)(resid + o0);
        float2 rv1 = *(const float2*)(resid + o1);
        v01.x += rv0.x; v01.y += rv0.y;
        v23.x += rv1.x; v23.y += rv1.y;
      }
      *(float2*)(C + o0) = v01;
      *(float2*)(C + o1) = v23;
    }
}

// ------------------- RoPE + bf16 hi/lo split (q and k) ---------------------
__global__ void rope_split_kernel(const float* __restrict__ src,
                                  __nv_bfloat16* __restrict__ hi,
                                  __nv_bfloat16* __restrict__ lo,
                                  int H, float scale, int total) {
  int idx = blockIdx.x * blockDim.x + threadIdx.x;
  if (idx >= total) return;
  int j = idx & 31;
  int tmp = idx >> 5;
  int hh = tmp % H;
  int s = tmp / H;
  float e = (2.0f * (float)j) / 64.0f;
  float inv_freq = powf(10000.0f, -e);
  float ang = (float)s * inv_freq;
  float c, sn;
  sincosf(ang, &sn, &c);
  size_t base = ((size_t)s * H + hh) * HD;
  float x1 = src[base + j];
  float x2 = src[base + j + 32];
  float y1 = (x1 * c - x2 * sn) * scale;
  float y2 = (x1 * sn + x2 * c) * scale;
  __nv_bfloat16 h1 = __float2bfloat16(y1);
  hi[base + j] = h1;
  lo[base + j] = __float2bfloat16(y1 - __bfloat162float(h1));
  __nv_bfloat16 h2 = __float2bfloat16(y2);
  hi[base + j + 32] = h2;
  lo[base + j + 32] = __float2bfloat16(y2 - __bfloat162float(h2));
}

// ------------- V split + transpose: [S][8][64] -> [8][64][S] bf16 ----------
__global__ void __launch_bounds__(256) split_vT_kernel(
    const float* __restrict__ v, __nv_bfloat16* __restrict__ th,
    __nv_bfloat16* __restrict__ tl) {
  __shared__ float t[32][33];
  int s0 = blockIdx.x * 32, d0 = blockIdx.y * 32, h = blockIdx.z;
  int tx = threadIdx.x & 31, ty = threadIdx.x >> 5;
  #pragma unroll
  for (int j = ty; j < 32; j += 8)
    t[j][tx] = v[((size_t)(s0 + j) * HKV + h) * HD + d0 + tx];
  __syncthreads();
  int j = threadIdx.x >> 3;
  int cg = threadIdx.x & 7;
  float v0 = t[cg * 4 + 0][j], v1 = t[cg * 4 + 1][j];
  float v2 = t[cg * 4 + 2][j], v3 = t[cg * 4 + 3][j];
  __nv_bfloat16 h0 = __float2bfloat16(v0), h1 = __float2bfloat16(v1);
  __nv_bfloat16 h2 = __float2bfloat16(v2), h3 = __float2bfloat16(v3);
  size_t o = ((size_t)h * HD + d0 + j) * S_LEN + s0 + cg * 4;
  *(uint2*)(th + o) = make_uint2(pack2bf(h0, h1), pack2bf(h2, h3));
  *(uint2*)(tl + o) = make_uint2(
      pack2bf(__float2bfloat16(v0 - __bfloat162float(h0)),
              __float2bfloat16(v1 - __bfloat162float(h1))),
      pack2bf(__float2bfloat16(v2 - __bfloat162float(h2)),
              __float2bfloat16(v3 - __bfloat162float(h3))));
}

// --------------------- Flash attention on HMMA (R13-best) ------------------
// CTA: (head, 64-q-row tile). 4 warps x 16 rows. K/V 64x64 tiles, 2 stages.
// smem: Qh@0, Ql@8K, stage s@16K+32K*s: {Kh, Kl, Vth, Vtl} x 8KB.
#define FLASH_SMEM (16384 + 2 * 32768 + 1024)

__global__ void __launch_bounds__(128) flash_hmma_kernel(
    const __nv_bfloat16* __restrict__ qh, const __nv_bfloat16* __restrict__ ql,
    const __nv_bfloat16* __restrict__ kh, const __nv_bfloat16* __restrict__ kl,
    const __nv_bfloat16* __restrict__ vth, const __nv_bfloat16* __restrict__ vtl,
    __nv_bfloat16* __restrict__ Ohi, __nv_bfloat16* __restrict__ Olo) {
  extern __shared__ char smem_raw[];
  uint32_t sb = smem_u32(smem_raw);
  uint32_t base = (sb + 1023) & ~1023u;

  int tid = threadIdx.x, lane = tid & 31, wid = tid >> 5;
  int h = blockIdx.x;
  int qt = gridDim.y - 1 - blockIdx.y;     // heavy tiles first
  int hk = h >> 2;
  int q0 = qt * 64;

  // Q tile (hi/lo), 4 x 16B chunks per thread per tile
  #pragma unroll
  for (int i = 0; i < 4; i++) {
    int idx = i * 128 + tid;
    int row = idx >> 3, ck = idx & 7;
    uint32_t so = SWZ128((uint32_t)(row * 128 + ck * 16));
    size_t gq = ((size_t)(q0 + row) * HQ + h) * HD + ck * 8;
    CP_ASYNC16(base + so, qh + gq);
    CP_ASYNC16(base + 8192 + so, ql + gq);
  }

  #define FL_LOAD(s, k0_)                                                     \
    do {                                                                      \
      uint32_t stb = base + 16384 + (uint32_t)(s) * 32768;                    \
      _Pragma("unroll")                                                       \
      for (int i = 0; i < 4; i++) {                                           \
        int idx = i * 128 + tid;                                              \
        int row = idx >> 3, ck = idx & 7;                                     \
        uint32_t so = SWZ128((uint32_t)(row * 128 + ck * 16));                \
        size_t gk = ((size_t)((k0_) + row) * HKV + hk) * HD + ck * 8;         \
        size_t gv = ((size_t)hk * HD + row) * S_LEN + (k0_) + ck * 8;         \
        CP_ASYNC16(stb + so, kh + gk);                                        \
        CP_ASYNC16(stb + 8192 + so, kl + gk);                                 \
        CP_ASYNC16(stb + 16384 + so, vth + gv);                               \
        CP_ASYNC16(stb + 24576 + so, vtl + gv);                               \
      }                                                                       \
    } while (0)

  FL_LOAD(0, 0);
  CP_COMMIT();

  int a_r = lane & 15, a_k = lane >> 4;
  int b_r = lane & 7, b_k = (lane >> 3) & 1;
  int r_in8 = lane >> 2;
  int c2 = (lane & 3) * 2;

  uint32_t qfh[4][4], qfl[4][4];
  float oacc[8][4];
  #pragma unroll
  for (int i = 0; i < 8; i++)
    #pragma unroll
    for (int j = 0; j < 4; j++) oacc[i][j] = 0.f;
  const float NEG_INF = __int_as_float(0xff800000);
  float m0 = NEG_INF, m1 = NEG_INF, l0 = 0.f, l1 = 0.f;

  for (int kt = 0; kt <= qt; kt++) {
    if (kt + 1 <= qt) {
      FL_LOAD((kt + 1) & 1, (kt + 1) * 64);
      CP_COMMIT();
      CP_WAIT1();
    } else {
      CP_WAIT0();
    }
    __syncthreads();
    uint32_t stb = base + 16384 + (uint32_t)(kt & 1) * 32768;

    if (kt == 0) {   // Q fragments, loaded once (same commit group as stage 0)
      #pragma unroll
      for (int ks = 0; ks < 4; ks++) {
        uint32_t off = SWZ128((uint32_t)((wid * 16 + a_r) * 128 +
                                         (ks * 2 + a_k) * 16));
        LDSM_X4(qfh[ks][0], qfh[ks][1], qfh[ks][2], qfh[ks][3], base + off);
        LDSM_X4(qfl[ks][0], qfl[ks][1], qfl[ks][2], qfl[ks][3],
                base + 8192 + off);
      }
    }

    // ---- S = Q K^T (x3 split), 16x64 per warp -----------------------------
    float sacc[8][4];
    #pragma unroll
    for (int i = 0; i < 8; i++)
      #pragma unroll
      for (int j = 0; j < 4; j++) sacc[i][j] = 0.f;

    #pragma unroll
    for (int ks = 0; ks < 4; ks++)
      #pragma unroll
      for (int nt = 0; nt < 8; nt++) {
        uint32_t off = SWZ128((uint32_t)((nt * 8 + b_r) * 128 +
                                         (ks * 2 + b_k) * 16));
        uint32_t kbh[2], kbl[2];
        LDSM_X2(kbh[0], kbh[1], stb + off);
        LDSM_X2(kbl[0], kbl[1], stb + 8192 + off);
        MMA16816(sacc[nt], qfh[ks], kbh);
        MMA16816(sacc[nt], qfl[ks], kbh);
        MMA16816(sacc[nt], qfh[ks], kbl);
      }

    int r0 = q0 + wid * 16 + r_in8;
    int r1 = r0 + 8;
    if (kt == qt) {    // causal mask on diagonal tile
      #pragma unroll
      for (int nt = 0; nt < 8; nt++) {
        int cg = kt * 64 + nt * 8 + c2;
        if (cg > r0)     sacc[nt][0] = NEG_INF;
        if (cg + 1 > r0) sacc[nt][1] = NEG_INF;
        if (cg > r1)     sacc[nt][2] = NEG_INF;
        if (cg + 1 > r1) sacc[nt][3] = NEG_INF;
      }
    }

    // ---- online softmax ---------------------------------------------------
    float mx0 = m0, mx1 = m1;
    #pragma unroll
    for (int nt = 0; nt < 8; nt++) {
      mx0 = fmaxf(mx0, fmaxf(sacc[nt][0], sacc[nt][1]));
      mx1 = fmaxf(mx1, fmaxf(sacc[nt][2], sacc[nt][3]));
    }
    mx0 = fmaxf(mx0, __shfl_xor_sync(0xffffffffu, mx0, 1));
    mx0 = fmaxf(mx0, __shfl_xor_sync(0xffffffffu, mx0, 2));
    mx1 = fmaxf(mx1, __shfl_xor_sync(0xffffffffu, mx1, 1));
    mx1 = fmaxf(mx1, __shfl_xor_sync(0xffffffffu, mx1, 2));
    float sc0 = __expf(m0 - mx0), sc1 = __expf(m1 - mx1);
    m0 = mx0; m1 = mx1;

    uint32_t pAh[16], pAl[16];
    float rs0 = 0.f, rs1 = 0.f;
    #pragma unroll
    for (int nt = 0; nt < 8; nt++) {
      float p0 = __expf(sacc[nt][0] - m0);
      float p1 = __expf(sacc[nt][1] - m0);
      float p2 = __expf(sacc[nt][2] - m1);
      float p3 = __expf(sacc[nt][3] - m1);
      rs0 += p0 + p1;
      rs1 += p2 + p3;
      __nv_bfloat16 b0 = __float2bfloat16(p0), b1 = __float2bfloat16(p1);
      __nv_bfloat16 b2 = __float2bfloat16(p2), b3 = __float2bfloat16(p3);
      pAh[nt * 2]     = pack2bf(b0, b1);
      pAh[nt * 2 + 1] = pack2bf(b2, b3);
      pAl[nt * 2]     = pack2bf(__float2bfloat16(p0 - __bfloat162float(b0)),
                                __float2bfloat16(p1 - __bfloat162float(b1)));
      pAl[nt * 2 + 1] = pack2bf(__float2bfloat16(p2 - __bfloat162float(b2)),
                                __float2bfloat16(p3 - __bfloat162float(b3)));
    }
    rs0 += __shfl_xor_sync(0xffffffffu, rs0, 1);
    rs0 += __shfl_xor_sync(0xffffffffu, rs0, 2);
    rs1 += __shfl_xor_sync(0xffffffffu, rs1, 1);
    rs1 += __shfl_xor_sync(0xffffffffu, rs1, 2);
    l0 = l0 * sc0 + rs0;
    l1 = l1 * sc1 + rs1;
    #pragma unroll
    for (int nt = 0; nt < 8; nt++) {
      oacc[nt][0] *= sc0; oacc[nt][1] *= sc0;
      oacc[nt][2] *= sc1; oacc[nt][3] *= sc1;
    }

    // ---- O += P V (x3 split); A-frag direct from S acc layout -------------
    #pragma unroll
    for (int ksp = 0; ksp < 4; ksp++)
      #pragma unroll
      for (int ntd = 0; ntd < 8; ntd++) {
        uint32_t off = SWZ128((uint32_t)((ntd * 8 + b_r) * 128 +
                                         (ksp * 2 + b_k) * 16));
        uint32_t vbh[2], vbl[2];
        LDSM_X2(vbh[0], vbh[1], stb + 16384 + off);
        LDSM_X2(vbl[0], vbl[1], stb + 24576 + off);
        MMA16816(oacc[ntd], &pAh[4 * ksp], vbh);
        MMA16816(oacc[ntd], &pAl[4 * ksp], vbh);
        MMA16816(oacc[ntd], &pAh[4 * ksp], vbl);
      }
    __syncthreads();
  }

  // ---- epilogue: normalize, split to bf16 hi/lo, store --------------------
  float inv0 = 1.f / l0, inv1 = 1.f / l1;
  int r0 = q0 + wid * 16 + r_in8;
  #pragma unroll
  for (int ntd = 0; ntd < 8; ntd++) {
    int col = h * HD + ntd * 8 + c2;
    float v00 = oacc[ntd][0] * inv0, v01 = oacc[ntd][1] * inv0;
    float v10 = oacc[ntd][2] * inv1, v11 = oacc[ntd][3] * inv1;
    __nv_bfloat16 h00 = __float2bfloat16(v00), h01 = __float2bfloat16(v01);
    __nv_bfloat16 h10 = __float2bfloat16(v10), h11 = __float2bfloat16(v11);
    size_t o0 = (size_t)r0 * DMODEL + col;
    size_t o1 = (size_t)(r0 + 8) * DMODEL + col;
    *(uint32_t*)(Ohi + o0) = pack2bf(h00, h01);
    *(uint32_t*)(Ohi + o1) = pack2bf(h10, h11);
    *(uint32_t*)(Olo + o0) =
        pack2bf(__float2bfloat16(v00 - __bfloat162float(h00)),
                __float2bfloat16(v01 - __bfloat162float(h01)));
    *(uint32_t*)(Olo + o1) =
        pack2bf(__float2bfloat16(v10 - __bfloat162float(h10)),
                __float2bfloat16(v11 - __bfloat162float(h11)));
  }
}

// ------------------------------ launch -------------------------------------
extern "C" void kernel_launch(void* const* d_in, const int* in_sizes, int n_in,
                              void* d_out, int out_size) {
  const float* x  = (const float*)d_in[0];
  const float* g  = (const float*)d_in[1];
  const float* wq = (const float*)d_in[2];
  const float* wk = (const float*)d_in[3];
  const float* wv = (const float*)d_in[4];
  const float* wo = (const float*)d_in[5];
  float* out = (float*)d_out;

  __nv_bfloat16 *hh, *hl, *wqh, *wql, *wkh, *wkl, *wvh, *wvl, *woh, *wol;
  __nv_bfloat16 *ohi, *olo, *qhp, *qlp, *khp, *klp, *vth, *vtl;
  float *q, *k, *v;
  cudaGetSymbolAddress((void**)&hh, g_h_hi);
  cudaGetSymbolAddress((void**)&hl, g_h_lo);
  cudaGetSymbolAddress((void**)&wqh, g_wqT_hi);
  cudaGetSymbolAddress((void**)&wql, g_wqT_lo);
  cudaGetSymbolAddress((void**)&wkh, g_wkT_hi);
  cudaGetSymbolAddress((void**)&wkl, g_wkT_lo);
  cudaGetSymbolAddress((void**)&wvh, g_wvT_hi);
  cudaGetSymbolAddress((void**)&wvl, g_wvT_lo);
  cudaGetSymbolAddress((void**)&woh, g_woT_hi);
  cudaGetSymbolAddress((void**)&wol, g_woT_lo);
  cudaGetSymbolAddress((void**)&ohi, g_o_hi);
  cudaGetSymbolAddress((void**)&olo, g_o_lo);
  cudaGetSymbolAddress((void**)&qhp, g_qh);
  cudaGetSymbolAddress((void**)&qlp, g_ql);
  cudaGetSymbolAddress((void**)&khp, g_kh);
  cudaGetSymbolAddress((void**)&klp, g_kl);
  cudaGetSymbolAddress((void**)&vth, g_vth);
  cudaGetSymbolAddress((void**)&vtl, g_vtl);
  cudaGetSymbolAddress((void**)&q, g_q);
  cudaGetSymbolAddress((void**)&k, g_k);
  cudaGetSymbolAddress((void**)&v, g_v);

  cudaFuncSetAttribute(mm_kernel, cudaFuncAttributeMaxDynamicSharedMemorySize,
                       MM_SMEM_BYTES);
  cudaFuncSetAttribute(flash_hmma_kernel,
                       cudaFuncAttributeMaxDynamicSharedMemorySize, FLASH_SMEM);

  // all weight transposes + bf16 hi/lo splits (one launch)
  transpose_all_kernel<<<10240, 256>>>(wq, wk, wv, wo, wqh, wql, wkh, wkl,
                                       wvh, wvl, woh, wol);

  // rmsnorm + split
  rmsnorm_split_kernel<<<S_LEN, 256>>>(x, g, hh, hl);

  // q/k/v projections (one fused HMMA launch: 16|4|4 column segments)
  mm_kernel<<<dim3(24, S_LEN / 128), 256, MM_SMEM_BYTES>>>(
      hh, hl, nullptr, DMODEL,
      wqh, wql, q, DMODEL, 16,
      wkh, wkl, k, KVDIM, 4,
      wvh, wvl, v, KVDIM);

  // rope + split (q scaled by 1/sqrt(64)=0.125, exact), v split+transpose
  {
    int totq = S_LEN * HQ * 32;
    rope_split_kernel<<<(totq + 255) / 256, 256>>>(q, qhp, qlp, HQ, 0.125f, totq);
    int totk = S_LEN * HKV * 32;
    rope_split_kernel<<<(totk + 255) / 256, 256>>>(k, khp, klp, HKV, 1.0f, totk);
    split_vT_kernel<<<dim3(S_LEN / 32, HD / 32, HKV), 256>>>(v, vth, vtl);
  }

  // causal flash attention on HMMA (GQA), writes bf16 hi/lo split
  flash_hmma_kernel<<<dim3(HQ, S_LEN / 64), 128, FLASH_SMEM>>>(
      qhp, qlp, khp, klp, vth, vtl, ohi, olo);

  // output projection + residual
  mm_kernel<<<dim3(16, S_LEN / 128), 256, MM_SMEM_BYTES>>>(
      ohi, olo, x, DMODEL,
      woh, wol, out, DMODEL, 16,
      nullptr, nullptr, nullptr, 0, 0,
      nullptr, nullptr, nullptr, 0);
}